// round 14
// baseline (speedup 1.0000x reference)
#include <cuda_runtime.h>
#include <cuda_fp16.h>
#include <math.h>
#include <stdint.h>

// Shapes
#define T_ 16
#define B_ 32
#define S_ 256
#define H_ 256
#define E_ 300
#define V_ 1000

// d_out packing (reference return order, flattened floats)
#define PROB_OFF 0
#define HT_OFF   512000
#define CT_OFF   520192
#define CTX_OFF  528384

// Scratch (device globals; no cudaMalloc allowed)
__device__ float g_xproj[512 * 1024];    // [t*32+b][4H]
__device__ float g_enct[8192 * 256];     // PERMUTED: [b*256+s][H] (masked tiles never read)
__device__ float g_outh[16 * 32 * 256];  // [t][b][h]
__device__ float g_comb[512 * 512];      // [t*32+b][2H]
__device__ float g_logits[512 * 1000];   // [t*32+b][V]
__device__ float g_WdT[256 * 256];       // Wd transposed: [k][h]
__device__ float g_scores[512 * 256];    // raw scores [(t*32+b)][s]

__device__ __forceinline__ float sigmoidf_(float x) {
    return 1.f / (1.f + __expf(-x));
}
__device__ __forceinline__ uint32_t smem_u32(const void* p) {
    uint32_t a;
    asm("{ .reg .u64 t; cvta.to.shared.u64 t, %1; cvt.u32.u64 %0, t; }"
        : "=r"(a) : "l"(p));
    return a;
}
__device__ __forceinline__ void st_cluster_f32(uint32_t addr, uint32_t rank, float v) {
    uint32_t remote;
    asm volatile("mapa.shared::cluster.u32 %0, %1, %2;"
                 : "=r"(remote) : "r"(addr), "r"(rank));
    asm volatile("st.shared::cluster.f32 [%0], %1;"
                 :: "r"(remote), "f"(v) : "memory");
}
__device__ __forceinline__ __half2 tanh_h2(__half2 x) {
    uint32_t xi = *reinterpret_cast<uint32_t*>(&x), yi;
    asm("tanh.approx.f16x2 %0, %1;" : "=r"(yi) : "r"(xi));
    return *reinterpret_cast<__half2*>(&yi);
}

// ---------------------------------------------------------------------------
// GEMM: C[M][N] = Arow(m) . Bw[n] + bias[n]   (B stored [N][K], i.e. C=A@B^T)
// Tile 64(M) x 64(N), TK=8, 128 threads, 8x4 register microtile.
// MODE 0: Arow(m)=A[m]
// MODE 1: Arow(m)=A[Aidx[m]]                  (embedding gather)
// ---------------------------------------------------------------------------
template <int MODE>
__global__ void __launch_bounds__(128)
gemm64_kernel(const float* __restrict__ A, const int* __restrict__ Aidx,
              const float* __restrict__ Bw, const float* __restrict__ bias,
              float* __restrict__ C, int M, int N, int K)
{
    __shared__ __align__(16) float As[8][64];
    __shared__ __align__(16) float Bs[8][64];

    int tid = threadIdx.x;
    int nbase = blockIdx.x * 64, mbase = blockIdx.y * 64;

    int lr  = tid >> 1;        // 0..63
    int lkq = (tid & 1) * 4;   // 0 or 4

    long arow;
    {
        int m = mbase + lr;
        arow = (MODE == 1) ? (long)Aidx[m] : (long)m;
    }
    const float* Ap = A + arow * (long)K;
    int bn = nbase + lr;
    const float* Bp = Bw + (long)bn * K;
    bool bval = (bn < N);

    int tx = tid & 15, ty = tid >> 4;

    float acc[8][4];
#pragma unroll
    for (int i = 0; i < 8; i++)
#pragma unroll
        for (int j = 0; j < 4; j++) acc[i][j] = 0.f;

    int ktiles = (K + 7) >> 3;

    float4 av = make_float4(0.f, 0.f, 0.f, 0.f);
    float4 bv = make_float4(0.f, 0.f, 0.f, 0.f);
    {
        int k = lkq;
        if (k + 3 < K) av = *(const float4*)(Ap + k);
        else { if (k < K) av.x = Ap[k]; if (k+1 < K) av.y = Ap[k+1];
               if (k+2 < K) av.z = Ap[k+2]; if (k+3 < K) av.w = Ap[k+3]; }
        if (bval) {
            if (k + 3 < K) bv = *(const float4*)(Bp + k);
            else { if (k < K) bv.x = Bp[k]; if (k+1 < K) bv.y = Bp[k+1];
                   if (k+2 < K) bv.z = Bp[k+2]; if (k+3 < K) bv.w = Bp[k+3]; }
        }
    }

    for (int kt = 0; kt < ktiles; ++kt) {
        __syncthreads();
        As[lkq + 0][lr] = av.x; As[lkq + 1][lr] = av.y;
        As[lkq + 2][lr] = av.z; As[lkq + 3][lr] = av.w;
        Bs[lkq + 0][lr] = bv.x; Bs[lkq + 1][lr] = bv.y;
        Bs[lkq + 2][lr] = bv.z; Bs[lkq + 3][lr] = bv.w;
        __syncthreads();

        av = make_float4(0.f, 0.f, 0.f, 0.f);
        bv = make_float4(0.f, 0.f, 0.f, 0.f);
        if (kt + 1 < ktiles) {
            int k = ((kt + 1) << 3) + lkq;
            if (k + 3 < K) av = *(const float4*)(Ap + k);
            else { if (k < K) av.x = Ap[k]; if (k+1 < K) av.y = Ap[k+1];
                   if (k+2 < K) av.z = Ap[k+2]; if (k+3 < K) av.w = Ap[k+3]; }
            if (bval) {
                if (k + 3 < K) bv = *(const float4*)(Bp + k);
                else { if (k < K) bv.x = Bp[k]; if (k+1 < K) bv.y = Bp[k+1];
                       if (k+2 < K) bv.z = Bp[k+2]; if (k+3 < K) bv.w = Bp[k+3]; }
            }
        }

#pragma unroll
        for (int k = 0; k < 8; ++k) {
            float4 a0 = *(const float4*)&As[k][ty * 4];
            float4 a1 = *(const float4*)&As[k][32 + ty * 4];
            float4 b  = *(const float4*)&Bs[k][tx * 4];
            acc[0][0] += a0.x * b.x; acc[0][1] += a0.x * b.y; acc[0][2] += a0.x * b.z; acc[0][3] += a0.x * b.w;
            acc[1][0] += a0.y * b.x; acc[1][1] += a0.y * b.y; acc[1][2] += a0.y * b.z; acc[1][3] += a0.y * b.w;
            acc[2][0] += a0.z * b.x; acc[2][1] += a0.z * b.y; acc[2][2] += a0.z * b.z; acc[2][3] += a0.z * b.w;
            acc[3][0] += a0.w * b.x; acc[3][1] += a0.w * b.y; acc[3][2] += a0.w * b.z; acc[3][3] += a0.w * b.w;
            acc[4][0] += a1.x * b.x; acc[4][1] += a1.x * b.y; acc[4][2] += a1.x * b.z; acc[4][3] += a1.x * b.w;
            acc[5][0] += a1.y * b.x; acc[5][1] += a1.y * b.y; acc[5][2] += a1.y * b.z; acc[5][3] += a1.y * b.w;
            acc[6][0] += a1.z * b.x; acc[6][1] += a1.z * b.y; acc[6][2] += a1.z * b.z; acc[6][3] += a1.z * b.w;
            acc[7][0] += a1.w * b.x; acc[7][1] += a1.w * b.y; acc[7][2] += a1.w * b.z; acc[7][3] += a1.w * b.w;
        }
    }

#pragma unroll
    for (int i = 0; i < 8; i++) {
        int mm = mbase + ((i < 4) ? (ty * 4 + i) : (32 + ty * 4 + (i - 4)));
#pragma unroll
        for (int j = 0; j < 4; j++) {
            int n = nbase + tx * 4 + j;
            if (n < N) C[(long)mm * N + n] = acc[i][j] + bias[n];
        }
    }
}

// Naive transpose: WdT[k][h] = Wd[h][k]  (256x256, tiny)
__global__ void transpose256_kernel(const float* __restrict__ in,
                                    float* __restrict__ out)
{
    int idx = blockIdx.x * 256 + threadIdx.x;  // idx = k*256 + h
    int k = idx >> 8, h = idx & 255;
    out[idx] = in[h * 256 + k];
}

// ---------------------------------------------------------------------------
// enc_t worker: 256-thread tile routine, synced by a NAMED barrier so two
// instances run concurrently in one 512-thread CTA.
// ---------------------------------------------------------------------------
__device__ void enc_worker(const float* __restrict__ enc,
                           const int* __restrict__ lens,
                           const float* __restrict__ We,
                           const float* __restrict__ be,
                           float* __restrict__ enct,
                           float* sm, int widx, int stride,
                           int tid, int barid)
{
    float* As = sm;         // [8][64]
    float* Bs = sm + 512;   // [8][64]
    int tx = tid & 15, ty = tid >> 4;   // ty 0..15
    int lr = tid >> 1, lkq = (tid & 1) * 4;

    for (int id = widx; id < 512; id += stride) {
        int mbase = (id >> 2) * 64, nbase = (id & 3) * 64;
        int bb = mbase >> 8;
        if ((mbase & 255) >= lens[bb]) continue;

        const float* Ap = enc;
        const float* Bp = We;
        if (tid < 128) {
            int m = mbase + lr;
            int s = m & 255, b2 = m >> 8;
            Ap = enc + ((long)s * 32 + b2) * 256;
            Bp = We + (long)(nbase + lr) * 256;
        }

        float acc[4][4];
#pragma unroll
        for (int i = 0; i < 4; i++)
#pragma unroll
            for (int j = 0; j < 4; j++) acc[i][j] = 0.f;

        float4 av = make_float4(0.f, 0.f, 0.f, 0.f);
        float4 bv = make_float4(0.f, 0.f, 0.f, 0.f);
        if (tid < 128) {
            av = *(const float4*)(Ap + lkq);
            bv = *(const float4*)(Bp + lkq);
        }

        for (int kt = 0; kt < 32; ++kt) {   // K=256
            asm volatile("bar.sync %0, 256;" :: "r"(barid) : "memory");
            if (tid < 128) {
                As[(lkq + 0) * 64 + lr] = av.x; As[(lkq + 1) * 64 + lr] = av.y;
                As[(lkq + 2) * 64 + lr] = av.z; As[(lkq + 3) * 64 + lr] = av.w;
                Bs[(lkq + 0) * 64 + lr] = bv.x; Bs[(lkq + 1) * 64 + lr] = bv.y;
                Bs[(lkq + 2) * 64 + lr] = bv.z; Bs[(lkq + 3) * 64 + lr] = bv.w;
            }
            asm volatile("bar.sync %0, 256;" :: "r"(barid) : "memory");

            if (tid < 128 && kt + 1 < 32) {
                int k = ((kt + 1) << 3) + lkq;
                av = *(const float4*)(Ap + k);
                bv = *(const float4*)(Bp + k);
            }

#pragma unroll
            for (int k = 0; k < 8; ++k) {
                float4 a = *(const float4*)&As[k * 64 + (ty << 2)];
                float4 b = *(const float4*)&Bs[k * 64 + (tx << 2)];
                acc[0][0] += a.x * b.x; acc[0][1] += a.x * b.y; acc[0][2] += a.x * b.z; acc[0][3] += a.x * b.w;
                acc[1][0] += a.y * b.x; acc[1][1] += a.y * b.y; acc[1][2] += a.y * b.z; acc[1][3] += a.y * b.w;
                acc[2][0] += a.z * b.x; acc[2][1] += a.z * b.y; acc[2][2] += a.z * b.z; acc[2][3] += a.z * b.w;
                acc[3][0] += a.w * b.x; acc[3][1] += a.w * b.y; acc[3][2] += a.w * b.z; acc[3][3] += a.w * b.w;
            }
        }

#pragma unroll
        for (int i = 0; i < 4; i++) {
            int m = mbase + (ty << 2) + i;
#pragma unroll
            for (int j = 0; j < 4; j++) {
                int n = nbase + (tx << 2) + j;
                enct[(long)m * 256 + n] = acc[i][j] + be[n];
            }
        }
        asm volatile("bar.sync %0, 256;" :: "r"(barid) : "memory");
    }
}

// ---------------------------------------------------------------------------
// Cluster LSTM (512 threads, k-split) + enc workers: grid 144 = 18 clusters x 8.
//   CTAs 0..63   : LSTM. thread = (row 128, batch-pair 2, k-half 2).
//   CTAs 64..143 : two concurrent enc_t tile workers per CTA (named barriers).
//
// LSTM smem (floats):
//   W_sm : [256][132] k-major, W_sm[k*132+row], row = g*32+ul      0..33791
//   h_sm : [2][4][264]  h_sm[buf*1056 + b*264 + k]                 33792..35903
//   g_sm : [2][4][132]  partial sums per k-half                    35904..36959
// ---------------------------------------------------------------------------
#define LSTM_HS 33792
#define LSTM_GS 35904
#define LSTM_SMEM_FLOATS 36960

__global__ void __launch_bounds__(512, 1) __cluster_dims__(8, 1, 1)
lstm_cluster_kernel(const float* __restrict__ xproj, const float* __restrict__ W_hh,
                    const float* __restrict__ b_hh, const float* __restrict__ h0,
                    const float* __restrict__ c0, float* __restrict__ outh,
                    float* __restrict__ comb,
                    float* __restrict__ dhT, float* __restrict__ dcT,
                    const float* __restrict__ enc, const int* __restrict__ lens,
                    const float* __restrict__ We, const float* __restrict__ be,
                    float* __restrict__ enct)
{
    extern __shared__ __align__(16) float sm[];
    int tid = threadIdx.x;

    if (blockIdx.x >= 64) {
        int half = tid >> 8;                    // 0 or 1
        enc_worker(enc, lens, We, be, enct,
                   sm + half * 1024,
                   (blockIdx.x - 64) * 2 + half, 160,
                   tid & 255, 1 + half);
        return;
    }

    float* W_sm = sm;
    uint32_t rank;
    asm("mov.u32 %0, %%cluster_ctarank;" : "=r"(rank));
    int B0 = (blockIdx.x >> 3) * 4;
    int u_base = 32 * (int)rank;

    for (int i = tid; i < 32768; i += 512) {
        int row = i >> 8, k = i & 255;
        int g = row >> 5, ul = row & 31;
        W_sm[k * 132 + row] = W_hh[(g * 256 + u_base + ul) * 256 + k];
    }
    for (int i = tid; i < 1024; i += 512) {
        int b = i >> 8, k = i & 255;
        sm[LSTM_HS + b * 264 + k] = h0[(B0 + b) * 256 + k];
    }

    float bh[4], cprev = 0.f;
    int ful = tid >> 2, fb = tid & 3;           // finalize mapping (tid < 128)
    if (tid < 128) {
#pragma unroll
        for (int g = 0; g < 4; g++) bh[g] = b_hh[g * 256 + u_base + ful];
        cprev = c0[(B0 + fb) * 256 + u_base + ful];
    }
    __syncthreads();
    asm volatile("barrier.cluster.arrive.aligned;" ::: "memory");
    asm volatile("barrier.cluster.wait.aligned;"   ::: "memory");

    uint32_t smb_hs = smem_u32(sm + LSTM_HS);

    int row = tid & 127;
    int bh2 = (tid >> 7) & 1;
    int kh  = tid >> 8;
    int kbase = kh * 128;

    for (int t = 0; t < 16; ++t) {
        int buf = t & 1;

        float xp[4];
        if (tid < 128) {
#pragma unroll
            for (int g = 0; g < 4; g++)
                xp[g] = __ldg(xproj + (long)(t * 32 + B0 + fb) * 1024
                                    + g * 256 + u_base + ful);
        }

        // dot: row x 2 batches, k in [kbase, kbase+128)
        const float* hA = sm + LSTM_HS + buf * 1056 + (bh2 * 2) * 264 + kbase;
        const float* hB = hA + 264;
        const float* Wp = W_sm + (long)kbase * 132 + row;
        float a0 = 0.f, a1 = 0.f;
#pragma unroll 8
        for (int kk = 0; kk < 128; kk += 4) {
            float w0 = Wp[(kk + 0) * 132];
            float w1 = Wp[(kk + 1) * 132];
            float w2 = Wp[(kk + 2) * 132];
            float w3 = Wp[(kk + 3) * 132];
            float4 ha = *(const float4*)(hA + kk);
            float4 hb = *(const float4*)(hB + kk);
            a0 += w0 * ha.x + w1 * ha.y + w2 * ha.z + w3 * ha.w;
            a1 += w0 * hb.x + w1 * hb.y + w2 * hb.z + w3 * hb.w;
        }
        sm[LSTM_GS + kh * 528 + (bh2 * 2 + 0) * 132 + row] = a0;
        sm[LSTM_GS + kh * 528 + (bh2 * 2 + 1) * 132 + row] = a1;
        __syncthreads();

        if (tid < 128) {
            const float* p0 = sm + LSTM_GS + fb * 132;
            const float* p1 = p0 + 528;
            float gi = p0[  0 + ful] + p1[  0 + ful] + xp[0] + bh[0];
            float gf = p0[ 32 + ful] + p1[ 32 + ful] + xp[1] + bh[1];
            float gg = p0[ 64 + ful] + p1[ 64 + ful] + xp[2] + bh[2];
            float go = p0[ 96 + ful] + p1[ 96 + ful] + xp[3] + bh[3];
            float c = sigmoidf_(gf) * cprev + sigmoidf_(gi) * tanhf(gg);
            float h = sigmoidf_(go) * tanhf(c);
            cprev = c;
            int hu = u_base + ful;
            int gb = B0 + fb;
            outh[t * 8192 + gb * 256 + hu] = h;
            comb[(t * 32 + gb) * 512 + 256 + hu] = h;
            if (t == 15) {
                dhT[gb * 256 + hu] = h;
                dcT[gb * 256 + hu] = c;
            } else {
                uint32_t off = smb_hs
                             + ((uint32_t)(((buf ^ 1) * 1056) + fb * 264 + hu) << 2);
#pragma unroll
                for (uint32_t r = 0; r < 8; r++) st_cluster_f32(off, r, h);
            }
        }

        if (t < 15) {
            asm volatile("barrier.cluster.arrive.aligned;" ::: "memory");
            asm volatile("barrier.cluster.wait.aligned;"   ::: "memory");
        }
    }
}

// ---------------------------------------------------------------------------
// Attention scores (load-balanced): grid (b=32, tg=4, sq=4), 256 threads.
// ---------------------------------------------------------------------------
__global__ void __launch_bounds__(256)
attn_scores_kernel(const float* __restrict__ enct,   // [b*256+s][H]
                   const float* __restrict__ outh,   // [t][b][h]
                   const float* __restrict__ WdT,    // [k][h]
                   const float* __restrict__ bd,
                   const float* __restrict__ wa,
                   const float* __restrict__ ba,
                   const int* __restrict__ lens,
                   float* __restrict__ scores)       // [(t*32+b)][s]
{
    __shared__ __align__(16) float outh_s[4][256];
    __shared__ __align__(16) float dec_s[4][256];
    __shared__ __align__(4) __half2 wa_h2[128];

    int b = blockIdx.x, t0 = blockIdx.y * 4, s0 = blockIdx.z * 64;
    int tid = threadIdx.x;
    int L = lens[b];
    if (s0 >= L) return;
    int send = min(s0 + 64, L);
    int w = tid >> 5, lane = tid & 31;

    {
        int j = tid >> 6, q = (tid & 63) * 4;
        float4 v = *(const float4*)(outh + (t0 + j) * 8192 + b * 256 + q);
        *(float4*)&outh_s[j][q] = v;
    }
    if (tid < 128)
        wa_h2[tid] = __floats2half2_rn(wa[2 * tid], wa[2 * tid + 1]);
    float bav = ba[0];
    __syncthreads();

    // dec_t: thread h = tid (fma pipe; overlaps other warps' MUFU)
    {
        float a0 = 0.f, a1 = 0.f, a2 = 0.f, a3 = 0.f;
#pragma unroll 4
        for (int k = 0; k < 256; k += 4) {
            float w0 = WdT[(k + 0) * 256 + tid];
            float w1 = WdT[(k + 1) * 256 + tid];
            float w2 = WdT[(k + 2) * 256 + tid];
            float w3 = WdT[(k + 3) * 256 + tid];
            float4 o0 = *(const float4*)&outh_s[0][k];
            float4 o1 = *(const float4*)&outh_s[1][k];
            float4 o2 = *(const float4*)&outh_s[2][k];
            float4 o3 = *(const float4*)&outh_s[3][k];
            a0 += w0 * o0.x + w1 * o0.y + w2 * o0.z + w3 * o0.w;
            a1 += w0 * o1.x + w1 * o1.y + w2 * o1.z + w3 * o1.w;
            a2 += w0 * o2.x + w1 * o2.y + w2 * o2.z + w3 * o2.w;
            a3 += w0 * o3.x + w1 * o3.y + w2 * o3.z + w3 * o3.w;
        }
        float bdv = bd[tid];
        dec_s[0][tid] = a0 + bdv;
        dec_s[1][tid] = a1 + bdv;
        dec_s[2][tid] = a2 + bdv;
        dec_s[3][tid] = a3 + bdv;
    }
    __syncthreads();

    float2 dpr[4][4];   // [j][t]
    __half2 wa2r[4];
#pragma unroll
    for (int j = 0; j < 4; j++) {
        int p = lane + 32 * j;
        wa2r[j] = wa_h2[p];
#pragma unroll
        for (int tt = 0; tt < 4; tt++)
            dpr[j][tt] = *(const float2*)&dec_s[tt][2 * p];
    }
    __half2 zero2 = __floats2half2_rn(0.f, 0.f);

    for (int s = s0 + w; s < send; s += 8) {
        const float2* eb2 = (const float2*)(enct + ((long)b * 256 + s) * 256);
        __half2 a0 = zero2, a1 = zero2, a2 = zero2, a3 = zero2;
#pragma unroll
        for (int j = 0; j < 4; j++) {
            float2 e = eb2[lane + 32 * j];
            __half2 w2 = wa2r[j];
            a0 = __hfma2(tanh_h2(__floats2half2_rn(e.x + dpr[j][0].x, e.y + dpr[j][0].y)), w2, a0);
            a1 = __hfma2(tanh_h2(__floats2half2_rn(e.x + dpr[j][1].x, e.y + dpr[j][1].y)), w2, a1);
            a2 = __hfma2(tanh_h2(__floats2half2_rn(e.x + dpr[j][2].x, e.y + dpr[j][2].y)), w2, a2);
            a3 = __hfma2(tanh_h2(__floats2half2_rn(e.x + dpr[j][3].x, e.y + dpr[j][3].y)), w2, a3);
        }
        float2 f0 = __half22float2(a0), f1 = __half22float2(a1);
        float2 f2 = __half22float2(a2), f3 = __half22float2(a3);
        float p0 = f0.x + f0.y, p1 = f1.x + f1.y;
        float p2 = f2.x + f2.y, p3 = f3.x + f3.y;
#pragma unroll
        for (int off = 16; off > 0; off >>= 1) {
            p0 += __shfl_xor_sync(0xffffffffu, p0, off);
            p1 += __shfl_xor_sync(0xffffffffu, p1, off);
            p2 += __shfl_xor_sync(0xffffffffu, p2, off);
            p3 += __shfl_xor_sync(0xffffffffu, p3, off);
        }
        if (lane == 0) {
            scores[((t0 + 0) * 32 + b) * 256 + s] = p0 + bav;
            scores[((t0 + 1) * 32 + b) * 256 + s] = p1 + bav;
            scores[((t0 + 2) * 32 + b) * 256 + s] = p2 + bav;
            scores[((t0 + 3) * 32 + b) * 256 + s] = p3 + bav;
        }
    }
}

// ---------------------------------------------------------------------------
// Attention softmax + context: grid (b=32, t=16) = 512 CTAs, 256 threads.
// ---------------------------------------------------------------------------
__global__ void __launch_bounds__(256)
attn_ctx_kernel(const float* __restrict__ scores,  // [(t*32+b)][s]
                const float* __restrict__ enc,     // [s*32+b][H]
                const int* __restrict__ lens,
                float* __restrict__ dctx,          // out + CTX_OFF, [b][t][h]
                float* __restrict__ comb)          // [t*32+b][2H]
{
    __shared__ float sc_s[256];
    __shared__ float red_s[8];

    int b = blockIdx.x, t = blockIdx.y, tid = threadIdx.x;
    int w = tid >> 5, lane = tid & 31;
    int L = lens[b];

    float x = (tid < L) ? scores[(t * 32 + b) * 256 + tid] : -1e30f;
    float m = x;
#pragma unroll
    for (int off = 16; off > 0; off >>= 1)
        m = fmaxf(m, __shfl_xor_sync(0xffffffffu, m, off));
    if (lane == 0) red_s[w] = m;
    __syncthreads();
    if (tid == 0) {
        float mm = red_s[0];
        for (int i = 1; i < 8; i++) mm = fmaxf(mm, red_s[i]);
        red_s[0] = mm;
    }
    __syncthreads();
    float mx = red_s[0];
    float e = (tid < L) ? __expf(x - mx) : 0.f;
    float sv = e;
#pragma unroll
    for (int off = 16; off > 0; off >>= 1)
        sv += __shfl_xor_sync(0xffffffffu, sv, off);
    __syncthreads();
    if (lane == 0) red_s[w] = sv;
    __syncthreads();
    if (tid == 0) {
        float ss = 0.f;
        for (int i = 0; i < 8; i++) ss += red_s[i];
        red_s[0] = ss;
    }
    __syncthreads();
    sc_s[tid] = e * (1.f / red_s[0]);
    __syncthreads();

    float c = 0.f;
    int s = 0;
    for (; s + 4 <= L; s += 4) {
        float v0 = enc[((long)(s + 0) * 32 + b) * 256 + tid];
        float v1 = enc[((long)(s + 1) * 32 + b) * 256 + tid];
        float v2 = enc[((long)(s + 2) * 32 + b) * 256 + tid];
        float v3 = enc[((long)(s + 3) * 32 + b) * 256 + tid];
        c += sc_s[s] * v0 + sc_s[s + 1] * v1 + sc_s[s + 2] * v2 + sc_s[s + 3] * v3;
    }
    for (; s < L; ++s)
        c += sc_s[s] * enc[((long)s * 32 + b) * 256 + tid];

    dctx[(b * 16 + t) * 256 + tid] = c;
    comb[(t * 32 + b) * 512 + tid] = c;
}

// softmax over V=1000 per row (512 rows)
__global__ void softmaxV_kernel(const float* __restrict__ logits,
                                float* __restrict__ prob)
{
    __shared__ float red_s[8];
    int m = blockIdx.x, tid = threadIdx.x, w = tid >> 5, lane = tid & 31;
    const float* row = logits + (long)m * 1000;

    float mx = -1e30f;
    for (int v = tid; v < 1000; v += 256) mx = fmaxf(mx, row[v]);
#pragma unroll
    for (int off = 16; off > 0; off >>= 1)
        mx = fmaxf(mx, __shfl_xor_sync(0xffffffffu, mx, off));
    if (lane == 0) red_s[w] = mx;
    __syncthreads();
    if (tid == 0) {
        float mm = red_s[0];
        for (int i = 1; i < 8; i++) mm = fmaxf(mm, red_s[i]);
        red_s[0] = mm;
    }
    __syncthreads();
    mx = red_s[0];

    float ebuf[4];
    float sum = 0.f;
    int cnt = 0;
    for (int v = tid; v < 1000; v += 256) {
        float e = __expf(row[v] - mx);
        ebuf[cnt++] = e;
        sum += e;
    }
#pragma unroll
    for (int off = 16; off > 0; off >>= 1)
        sum += __shfl_xor_sync(0xffffffffu, sum, off);
    __syncthreads();
    if (lane == 0) red_s[w] = sum;
    __syncthreads();
    if (tid == 0) {
        float ss = 0.f;
        for (int i = 0; i < 8; i++) ss += red_s[i];
        red_s[0] = ss;
    }
    __syncthreads();
    float inv = 1.f / red_s[0];
    cnt = 0;
    for (int v = tid; v < 1000; v += 256)
        prob[(long)m * 1000 + v] = ebuf[cnt++] * inv;
}

extern "C" void kernel_launch(void* const* d_in, const int* in_sizes, int n_in,
                              void* d_out, int out_size)
{
    const int*   target = (const int*)  d_in[0];
    const float* h0     = (const float*)d_in[1];
    const float* c0     = (const float*)d_in[2];
    const float* enc    = (const float*)d_in[3];
    const int*   lens   = (const int*)  d_in[4];
    const float* emb    = (const float*)d_in[5];
    const float* W_ih   = (const float*)d_in[6];
    const float* W_hh   = (const float*)d_in[7];
    const float* b_ih   = (const float*)d_in[8];
    const float* b_hh   = (const float*)d_in[9];
    const float* We     = (const float*)d_in[10];
    const float* be     = (const float*)d_in[11];
    const float* Wd     = (const float*)d_in[12];
    const float* bd     = (const float*)d_in[13];
    const float* wa     = (const float*)d_in[14];
    const float* ba     = (const float*)d_in[15];
    const float* W_out  = (const float*)d_in[16];
    const float* b_out  = (const float*)d_in[17];
    float* out = (float*)d_out;

    float* xproj  = nullptr; cudaGetSymbolAddress((void**)&xproj,  g_xproj);
    float* enct   = nullptr; cudaGetSymbolAddress((void**)&enct,   g_enct);
    float* outh   = nullptr; cudaGetSymbolAddress((void**)&outh,   g_outh);
    float* comb   = nullptr; cudaGetSymbolAddress((void**)&comb,   g_comb);
    float* logits = nullptr; cudaGetSymbolAddress((void**)&logits, g_logits);
    float* WdT    = nullptr; cudaGetSymbolAddress((void**)&WdT,    g_WdT);
    float* scr    = nullptr; cudaGetSymbolAddress((void**)&scr,    g_scores);

    const int LSTM_SMEM = LSTM_SMEM_FLOATS * 4;   // 147840 bytes
    static int smem_set = 0;
    if (!smem_set) {
        cudaFuncSetAttribute(lstm_cluster_kernel,
                             cudaFuncAttributeMaxDynamicSharedMemorySize, LSTM_SMEM);
        smem_set = 1;
    }

    // 0) WdT = Wd^T (tiny; needed by attn_scores)
    transpose256_kernel<<<256, 256>>>(Wd, WdT);
    // 1) x_proj = emb[target] @ W_ih^T + b_ih   [512 x 1024], K=300
    gemm64_kernel<1><<<dim3(16, 8), 128>>>(emb, target, W_ih, b_ih,
                                           xproj, 512, 1024, 300);
    // 2) cluster LSTM (CTAs 0..63, 512 thr) + enc_t workers (CTAs 64..143, 2x tiles)
    lstm_cluster_kernel<<<144, 512, LSTM_SMEM>>>(xproj, W_hh, b_hh, h0, c0,
                                                 outh, comb,
                                                 out + HT_OFF, out + CT_OFF,
                                                 enc, lens, We, be, enct);
    // 3a) scores (load-balanced s-quarters)
    attn_scores_kernel<<<dim3(32, 4, 4), 256>>>(enct, outh, WdT, bd, wa, ba,
                                                lens, scr);
    // 3b) softmax + context -> out[CTX], comb(left)
    attn_ctx_kernel<<<dim3(32, 16), 256>>>(scr, enc, lens,
                                           out + CTX_OFF, comb);
    // 4) logits = comb @ W_out^T + b_out   [512 x 1000], K=512
    gemm64_kernel<0><<<dim3(16, 8), 128>>>(comb, nullptr, W_out, b_out,
                                           logits, 512, 1000, 512);
    // 5) softmax over V -> out[PROB]
    softmaxV_kernel<<<512, 256>>>(logits, out + PROB_OFF);
}

// round 15
// speedup vs baseline: 1.0117x; 1.0117x over previous
#include <cuda_runtime.h>
#include <cuda_fp16.h>
#include <math.h>
#include <stdint.h>

// Shapes
#define T_ 16
#define B_ 32
#define S_ 256
#define H_ 256
#define E_ 300
#define V_ 1000

// d_out packing (reference return order, flattened floats)
#define PROB_OFF 0
#define HT_OFF   512000
#define CT_OFF   520192
#define CTX_OFF  528384

// Scratch (device globals; no cudaMalloc allowed)
__device__ float g_xproj[512 * 1024];    // [t*32+b][4H]
__device__ float g_enct[8192 * 256];     // PERMUTED: [b*256+s][H] (masked tiles never read)
__device__ float g_outh[16 * 32 * 256];  // [t][b][h]
__device__ float g_comb[512 * 512];      // [t*32+b][2H]
__device__ float g_logits[512 * 1000];   // [t*32+b][V]
__device__ float g_WdT[256 * 256];       // Wd transposed: [k][h]
__device__ float g_scores[512 * 256];    // raw scores [(t*32+b)][s]

__device__ __forceinline__ float sigmoidf_(float x) {
    return 1.f / (1.f + __expf(-x));
}
__device__ __forceinline__ uint32_t smem_u32(const void* p) {
    uint32_t a;
    asm("{ .reg .u64 t; cvta.to.shared.u64 t, %1; cvt.u32.u64 %0, t; }"
        : "=r"(a) : "l"(p));
    return a;
}
__device__ __forceinline__ void st_cluster_f32(uint32_t addr, uint32_t rank, float v) {
    uint32_t remote;
    asm volatile("mapa.shared::cluster.u32 %0, %1, %2;"
                 : "=r"(remote) : "r"(addr), "r"(rank));
    asm volatile("st.shared::cluster.f32 [%0], %1;"
                 :: "r"(remote), "f"(v) : "memory");
}
__device__ __forceinline__ __half2 tanh_h2(__half2 x) {
    uint32_t xi = *reinterpret_cast<uint32_t*>(&x), yi;
    asm("tanh.approx.f16x2 %0, %1;" : "=r"(yi) : "r"(xi));
    return *reinterpret_cast<__half2*>(&yi);
}

// ---------------------------------------------------------------------------
// GEMM: C[M][N] = Arow(m) . Bw[n] + bias[n]   (B stored [N][K], i.e. C=A@B^T)
// Tile 64(M) x 64(N), TK=8, 128 threads, 8x4 register microtile.
// MODE 0: Arow(m)=A[m]
// MODE 1: Arow(m)=A[Aidx[m]]                  (embedding gather)
// ---------------------------------------------------------------------------
template <int MODE>
__global__ void __launch_bounds__(128)
gemm64_kernel(const float* __restrict__ A, const int* __restrict__ Aidx,
              const float* __restrict__ Bw, const float* __restrict__ bias,
              float* __restrict__ C, int M, int N, int K)
{
    __shared__ __align__(16) float As[8][64];
    __shared__ __align__(16) float Bs[8][64];

    int tid = threadIdx.x;
    int nbase = blockIdx.x * 64, mbase = blockIdx.y * 64;

    int lr  = tid >> 1;        // 0..63
    int lkq = (tid & 1) * 4;   // 0 or 4

    long arow;
    {
        int m = mbase + lr;
        arow = (MODE == 1) ? (long)Aidx[m] : (long)m;
    }
    const float* Ap = A + arow * (long)K;
    int bn = nbase + lr;
    const float* Bp = Bw + (long)bn * K;
    bool bval = (bn < N);

    int tx = tid & 15, ty = tid >> 4;

    float acc[8][4];
#pragma unroll
    for (int i = 0; i < 8; i++)
#pragma unroll
        for (int j = 0; j < 4; j++) acc[i][j] = 0.f;

    int ktiles = (K + 7) >> 3;

    float4 av = make_float4(0.f, 0.f, 0.f, 0.f);
    float4 bv = make_float4(0.f, 0.f, 0.f, 0.f);
    {
        int k = lkq;
        if (k + 3 < K) av = *(const float4*)(Ap + k);
        else { if (k < K) av.x = Ap[k]; if (k+1 < K) av.y = Ap[k+1];
               if (k+2 < K) av.z = Ap[k+2]; if (k+3 < K) av.w = Ap[k+3]; }
        if (bval) {
            if (k + 3 < K) bv = *(const float4*)(Bp + k);
            else { if (k < K) bv.x = Bp[k]; if (k+1 < K) bv.y = Bp[k+1];
                   if (k+2 < K) bv.z = Bp[k+2]; if (k+3 < K) bv.w = Bp[k+3]; }
        }
    }

    for (int kt = 0; kt < ktiles; ++kt) {
        __syncthreads();
        As[lkq + 0][lr] = av.x; As[lkq + 1][lr] = av.y;
        As[lkq + 2][lr] = av.z; As[lkq + 3][lr] = av.w;
        Bs[lkq + 0][lr] = bv.x; Bs[lkq + 1][lr] = bv.y;
        Bs[lkq + 2][lr] = bv.z; Bs[lkq + 3][lr] = bv.w;
        __syncthreads();

        av = make_float4(0.f, 0.f, 0.f, 0.f);
        bv = make_float4(0.f, 0.f, 0.f, 0.f);
        if (kt + 1 < ktiles) {
            int k = ((kt + 1) << 3) + lkq;
            if (k + 3 < K) av = *(const float4*)(Ap + k);
            else { if (k < K) av.x = Ap[k]; if (k+1 < K) av.y = Ap[k+1];
                   if (k+2 < K) av.z = Ap[k+2]; if (k+3 < K) av.w = Ap[k+3]; }
            if (bval) {
                if (k + 3 < K) bv = *(const float4*)(Bp + k);
                else { if (k < K) bv.x = Bp[k]; if (k+1 < K) bv.y = Bp[k+1];
                       if (k+2 < K) bv.z = Bp[k+2]; if (k+3 < K) bv.w = Bp[k+3]; }
            }
        }

#pragma unroll
        for (int k = 0; k < 8; ++k) {
            float4 a0 = *(const float4*)&As[k][ty * 4];
            float4 a1 = *(const float4*)&As[k][32 + ty * 4];
            float4 b  = *(const float4*)&Bs[k][tx * 4];
            acc[0][0] += a0.x * b.x; acc[0][1] += a0.x * b.y; acc[0][2] += a0.x * b.z; acc[0][3] += a0.x * b.w;
            acc[1][0] += a0.y * b.x; acc[1][1] += a0.y * b.y; acc[1][2] += a0.y * b.z; acc[1][3] += a0.y * b.w;
            acc[2][0] += a0.z * b.x; acc[2][1] += a0.z * b.y; acc[2][2] += a0.z * b.z; acc[2][3] += a0.z * b.w;
            acc[3][0] += a0.w * b.x; acc[3][1] += a0.w * b.y; acc[3][2] += a0.w * b.z; acc[3][3] += a0.w * b.w;
            acc[4][0] += a1.x * b.x; acc[4][1] += a1.x * b.y; acc[4][2] += a1.x * b.z; acc[4][3] += a1.x * b.w;
            acc[5][0] += a1.y * b.x; acc[5][1] += a1.y * b.y; acc[5][2] += a1.y * b.z; acc[5][3] += a1.y * b.w;
            acc[6][0] += a1.z * b.x; acc[6][1] += a1.z * b.y; acc[6][2] += a1.z * b.z; acc[6][3] += a1.z * b.w;
            acc[7][0] += a1.w * b.x; acc[7][1] += a1.w * b.y; acc[7][2] += a1.w * b.z; acc[7][3] += a1.w * b.w;
        }
    }

#pragma unroll
    for (int i = 0; i < 8; i++) {
        int mm = mbase + ((i < 4) ? (ty * 4 + i) : (32 + ty * 4 + (i - 4)));
#pragma unroll
        for (int j = 0; j < 4; j++) {
            int n = nbase + tx * 4 + j;
            if (n < N) C[(long)mm * N + n] = acc[i][j] + bias[n];
        }
    }
}

// Naive transpose: WdT[k][h] = Wd[h][k]  (256x256, tiny)
__global__ void transpose256_kernel(const float* __restrict__ in,
                                    float* __restrict__ out)
{
    int idx = blockIdx.x * 256 + threadIdx.x;  // idx = k*256 + h
    int k = idx >> 8, h = idx & 255;
    out[idx] = in[h * 256 + k];
}

// ---------------------------------------------------------------------------
// enc_t worker (worker CTAs of the lstm launch). 256 threads, 4x4 microtile.
// ---------------------------------------------------------------------------
__device__ void enc_worker(const float* __restrict__ enc,
                           const int* __restrict__ lens,
                           const float* __restrict__ We,
                           const float* __restrict__ be,
                           float* __restrict__ enct,
                           float* sm, int widx, int stride)
{
    float* As = sm;         // [8][64]
    float* Bs = sm + 512;   // [8][64]
    int tid = threadIdx.x;
    int tx = tid & 15, ty = tid >> 4;
    int lr = tid >> 1, lkq = (tid & 1) * 4;

    for (int id = widx; id < 512; id += stride) {
        int mbase = (id >> 2) * 64, nbase = (id & 3) * 64;
        int bb = mbase >> 8;
        if ((mbase & 255) >= lens[bb]) continue;

        const float* Ap = enc;
        const float* Bp = We;
        if (tid < 128) {
            int m = mbase + lr;
            int s = m & 255, b2 = m >> 8;
            Ap = enc + ((long)s * 32 + b2) * 256;
            Bp = We + (long)(nbase + lr) * 256;
        }

        float acc[4][4];
#pragma unroll
        for (int i = 0; i < 4; i++)
#pragma unroll
            for (int j = 0; j < 4; j++) acc[i][j] = 0.f;

        float4 av = make_float4(0.f, 0.f, 0.f, 0.f);
        float4 bv = make_float4(0.f, 0.f, 0.f, 0.f);
        if (tid < 128) {
            av = *(const float4*)(Ap + lkq);
            bv = *(const float4*)(Bp + lkq);
        }

        for (int kt = 0; kt < 32; ++kt) {   // K=256
            __syncthreads();
            if (tid < 128) {
                As[(lkq + 0) * 64 + lr] = av.x; As[(lkq + 1) * 64 + lr] = av.y;
                As[(lkq + 2) * 64 + lr] = av.z; As[(lkq + 3) * 64 + lr] = av.w;
                Bs[(lkq + 0) * 64 + lr] = bv.x; Bs[(lkq + 1) * 64 + lr] = bv.y;
                Bs[(lkq + 2) * 64 + lr] = bv.z; Bs[(lkq + 3) * 64 + lr] = bv.w;
            }
            __syncthreads();

            if (tid < 128 && kt + 1 < 32) {
                int k = ((kt + 1) << 3) + lkq;
                av = *(const float4*)(Ap + k);
                bv = *(const float4*)(Bp + k);
            }

#pragma unroll
            for (int k = 0; k < 8; ++k) {
                float4 a = *(const float4*)&As[k * 64 + (ty << 2)];
                float4 b = *(const float4*)&Bs[k * 64 + (tx << 2)];
                acc[0][0] += a.x * b.x; acc[0][1] += a.x * b.y; acc[0][2] += a.x * b.z; acc[0][3] += a.x * b.w;
                acc[1][0] += a.y * b.x; acc[1][1] += a.y * b.y; acc[1][2] += a.y * b.z; acc[1][3] += a.y * b.w;
                acc[2][0] += a.z * b.x; acc[2][1] += a.z * b.y; acc[2][2] += a.z * b.z; acc[2][3] += a.z * b.w;
                acc[3][0] += a.w * b.x; acc[3][1] += a.w * b.y; acc[3][2] += a.w * b.z; acc[3][3] += a.w * b.w;
            }
        }

#pragma unroll
        for (int i = 0; i < 4; i++) {
            int m = mbase + (ty << 2) + i;
#pragma unroll
            for (int j = 0; j < 4; j++) {
                int n = nbase + (tx << 2) + j;
                enct[(long)m * 256 + n] = acc[i][j] + be[n];
            }
        }
        __syncthreads();
    }
}

// ---------------------------------------------------------------------------
// Cluster LSTM + enc workers: grid 136 = 17 clusters x 8 CTAs.
//   CTAs 0..63   : LSTM (proven R10/R12 code, unchanged).
//   CTAs 64..135 : enc_t tile workers (72 CTAs; no cluster interaction).
// 17 clusters fit in ONE wave under the same-die placement rule (8 + 9 on the
// 70/78-SM dies); 18 clusters spill a cluster into wave 2.
// ---------------------------------------------------------------------------
#define LSTM_HS 33792
#define LSTM_GS 35904
#define LSTM_SMEM_FLOATS 36432

__global__ void __launch_bounds__(256, 1) __cluster_dims__(8, 1, 1)
lstm_cluster_kernel(const float* __restrict__ xproj, const float* __restrict__ W_hh,
                    const float* __restrict__ b_hh, const float* __restrict__ h0,
                    const float* __restrict__ c0, float* __restrict__ outh,
                    float* __restrict__ comb,
                    float* __restrict__ dhT, float* __restrict__ dcT,
                    const float* __restrict__ enc, const int* __restrict__ lens,
                    const float* __restrict__ We, const float* __restrict__ be,
                    float* __restrict__ enct)
{
    extern __shared__ __align__(16) float sm[];
    int tid = threadIdx.x;

    if (blockIdx.x >= 64) {
        enc_worker(enc, lens, We, be, enct, sm, blockIdx.x - 64, 72);
        return;
    }

    float* W_sm = sm;
    uint32_t rank;
    asm("mov.u32 %0, %%cluster_ctarank;" : "=r"(rank));
    int B0 = (blockIdx.x >> 3) * 4;
    int u_base = 32 * (int)rank;

    for (int i = tid; i < 32768; i += 256) {
        int row = i >> 8, k = i & 255;
        int g = row >> 5, ul = row & 31;
        W_sm[k * 132 + row] = W_hh[(g * 256 + u_base + ul) * 256 + k];
    }
    for (int i = tid; i < 1024; i += 256) {
        int b = i >> 8, k = i & 255;
        sm[LSTM_HS + b * 264 + k] = h0[(B0 + b) * 256 + k];
    }

    float bh[4], cprev = 0.f;
    int ful = tid >> 2, fb = tid & 3;
    if (tid < 128) {
#pragma unroll
        for (int g = 0; g < 4; g++) bh[g] = b_hh[g * 256 + u_base + ful];
        cprev = c0[(B0 + fb) * 256 + u_base + ful];
    }
    __syncthreads();
    asm volatile("barrier.cluster.arrive.aligned;" ::: "memory");
    asm volatile("barrier.cluster.wait.aligned;"   ::: "memory");

    uint32_t smb_hs = smem_u32(sm + LSTM_HS);

    int row = tid & 127;
    int bh2 = tid >> 7;

    for (int t = 0; t < 16; ++t) {
        int buf = t & 1;

        float xp[4];
        if (tid < 128) {
#pragma unroll
            for (int g = 0; g < 4; g++)
                xp[g] = __ldg(xproj + (long)(t * 32 + B0 + fb) * 1024
                                    + g * 256 + u_base + ful);
        }

        const float* hA = sm + LSTM_HS + buf * 1056 + (bh2 * 2) * 264;
        const float* hB = hA + 264;
        float a0 = 0.f, a1 = 0.f;
#pragma unroll 8
        for (int k = 0; k < 256; k += 4) {
            float w0 = W_sm[(k + 0) * 132 + row];
            float w1 = W_sm[(k + 1) * 132 + row];
            float w2 = W_sm[(k + 2) * 132 + row];
            float w3 = W_sm[(k + 3) * 132 + row];
            float4 ha = *(const float4*)(hA + k);
            float4 hb = *(const float4*)(hB + k);
            a0 += w0 * ha.x + w1 * ha.y + w2 * ha.z + w3 * ha.w;
            a1 += w0 * hb.x + w1 * hb.y + w2 * hb.z + w3 * hb.w;
        }
        sm[LSTM_GS + (bh2 * 2 + 0) * 132 + row] = a0;
        sm[LSTM_GS + (bh2 * 2 + 1) * 132 + row] = a1;
        __syncthreads();

        if (tid < 128) {
            float gi = sm[LSTM_GS + fb * 132 +  0 + ful] + xp[0] + bh[0];
            float gf = sm[LSTM_GS + fb * 132 + 32 + ful] + xp[1] + bh[1];
            float gg = sm[LSTM_GS + fb * 132 + 64 + ful] + xp[2] + bh[2];
            float go = sm[LSTM_GS + fb * 132 + 96 + ful] + xp[3] + bh[3];
            float c = sigmoidf_(gf) * cprev + sigmoidf_(gi) * tanhf(gg);
            float h = sigmoidf_(go) * tanhf(c);
            cprev = c;
            int hu = u_base + ful;
            int gb = B0 + fb;
            outh[t * 8192 + gb * 256 + hu] = h;
            comb[(t * 32 + gb) * 512 + 256 + hu] = h;
            if (t == 15) {
                dhT[gb * 256 + hu] = h;
                dcT[gb * 256 + hu] = c;
            } else {
                uint32_t off = smb_hs
                             + ((uint32_t)(((buf ^ 1) * 1056) + fb * 264 + hu) << 2);
#pragma unroll
                for (uint32_t r = 0; r < 8; r++) st_cluster_f32(off, r, h);
            }
        }

        if (t < 15) {
            asm volatile("barrier.cluster.arrive.aligned;" ::: "memory");
            asm volatile("barrier.cluster.wait.aligned;"   ::: "memory");
        }
    }
}

// ---------------------------------------------------------------------------
// Attention scores (load-balanced): grid (b=32, tg=4, sq=4), 256 threads.
// ---------------------------------------------------------------------------
__global__ void __launch_bounds__(256)
attn_scores_kernel(const float* __restrict__ enct,   // [b*256+s][H]
                   const float* __restrict__ outh,   // [t][b][h]
                   const float* __restrict__ WdT,    // [k][h]
                   const float* __restrict__ bd,
                   const float* __restrict__ wa,
                   const float* __restrict__ ba,
                   const int* __restrict__ lens,
                   float* __restrict__ scores)       // [(t*32+b)][s]
{
    __shared__ __align__(16) float outh_s[4][256];
    __shared__ __align__(16) float dec_s[4][256];
    __shared__ __align__(4) __half2 wa_h2[128];

    int b = blockIdx.x, t0 = blockIdx.y * 4, s0 = blockIdx.z * 64;
    int tid = threadIdx.x;
    int L = lens[b];
    if (s0 >= L) return;
    int send = min(s0 + 64, L);
    int w = tid >> 5, lane = tid & 31;

    {
        int j = tid >> 6, q = (tid & 63) * 4;
        float4 v = *(const float4*)(outh + (t0 + j) * 8192 + b * 256 + q);
        *(float4*)&outh_s[j][q] = v;
    }
    if (tid < 128)
        wa_h2[tid] = __floats2half2_rn(wa[2 * tid], wa[2 * tid + 1]);
    float bav = ba[0];
    __syncthreads();

    // dec_t: thread h = tid (fma pipe; overlaps other warps' MUFU)
    {
        float a0 = 0.f, a1 = 0.f, a2 = 0.f, a3 = 0.f;
#pragma unroll 4
        for (int k = 0; k < 256; k += 4) {
            float w0 = WdT[(k + 0) * 256 + tid];
            float w1 = WdT[(k + 1) * 256 + tid];
            float w2 = WdT[(k + 2) * 256 + tid];
            float w3 = WdT[(k + 3) * 256 + tid];
            float4 o0 = *(const float4*)&outh_s[0][k];
            float4 o1 = *(const float4*)&outh_s[1][k];
            float4 o2 = *(const float4*)&outh_s[2][k];
            float4 o3 = *(const float4*)&outh_s[3][k];
            a0 += w0 * o0.x + w1 * o0.y + w2 * o0.z + w3 * o0.w;
            a1 += w0 * o1.x + w1 * o1.y + w2 * o1.z + w3 * o1.w;
            a2 += w0 * o2.x + w1 * o2.y + w2 * o2.z + w3 * o2.w;
            a3 += w0 * o3.x + w1 * o3.y + w2 * o3.z + w3 * o3.w;
        }
        float bdv = bd[tid];
        dec_s[0][tid] = a0 + bdv;
        dec_s[1][tid] = a1 + bdv;
        dec_s[2][tid] = a2 + bdv;
        dec_s[3][tid] = a3 + bdv;
    }
    __syncthreads();

    float2 dpr[4][4];   // [j][t]
    __half2 wa2r[4];
#pragma unroll
    for (int j = 0; j < 4; j++) {
        int p = lane + 32 * j;
        wa2r[j] = wa_h2[p];
#pragma unroll
        for (int tt = 0; tt < 4; tt++)
            dpr[j][tt] = *(const float2*)&dec_s[tt][2 * p];
    }
    __half2 zero2 = __floats2half2_rn(0.f, 0.f);

    for (int s = s0 + w; s < send; s += 8) {
        const float2* eb2 = (const float2*)(enct + ((long)b * 256 + s) * 256);
        __half2 a0 = zero2, a1 = zero2, a2 = zero2, a3 = zero2;
#pragma unroll
        for (int j = 0; j < 4; j++) {
            float2 e = eb2[lane + 32 * j];
            __half2 w2 = wa2r[j];
            a0 = __hfma2(tanh_h2(__floats2half2_rn(e.x + dpr[j][0].x, e.y + dpr[j][0].y)), w2, a0);
            a1 = __hfma2(tanh_h2(__floats2half2_rn(e.x + dpr[j][1].x, e.y + dpr[j][1].y)), w2, a1);
            a2 = __hfma2(tanh_h2(__floats2half2_rn(e.x + dpr[j][2].x, e.y + dpr[j][2].y)), w2, a2);
            a3 = __hfma2(tanh_h2(__floats2half2_rn(e.x + dpr[j][3].x, e.y + dpr[j][3].y)), w2, a3);
        }
        float2 f0 = __half22float2(a0), f1 = __half22float2(a1);
        float2 f2 = __half22float2(a2), f3 = __half22float2(a3);
        float p0 = f0.x + f0.y, p1 = f1.x + f1.y;
        float p2 = f2.x + f2.y, p3 = f3.x + f3.y;
#pragma unroll
        for (int off = 16; off > 0; off >>= 1) {
            p0 += __shfl_xor_sync(0xffffffffu, p0, off);
            p1 += __shfl_xor_sync(0xffffffffu, p1, off);
            p2 += __shfl_xor_sync(0xffffffffu, p2, off);
            p3 += __shfl_xor_sync(0xffffffffu, p3, off);
        }
        if (lane == 0) {
            scores[((t0 + 0) * 32 + b) * 256 + s] = p0 + bav;
            scores[((t0 + 1) * 32 + b) * 256 + s] = p1 + bav;
            scores[((t0 + 2) * 32 + b) * 256 + s] = p2 + bav;
            scores[((t0 + 3) * 32 + b) * 256 + s] = p3 + bav;
        }
    }
}

// ---------------------------------------------------------------------------
// Attention softmax + context: grid (b=32, t=16) = 512 CTAs, 256 threads.
// ---------------------------------------------------------------------------
__global__ void __launch_bounds__(256)
attn_ctx_kernel(const float* __restrict__ scores,  // [(t*32+b)][s]
                const float* __restrict__ enc,     // [s*32+b][H]
                const int* __restrict__ lens,
                float* __restrict__ dctx,          // out + CTX_OFF, [b][t][h]
                float* __restrict__ comb)          // [t*32+b][2H]
{
    __shared__ float sc_s[256];
    __shared__ float red_s[8];

    int b = blockIdx.x, t = blockIdx.y, tid = threadIdx.x;
    int w = tid >> 5, lane = tid & 31;
    int L = lens[b];

    float x = (tid < L) ? scores[(t * 32 + b) * 256 + tid] : -1e30f;
    float m = x;
#pragma unroll
    for (int off = 16; off > 0; off >>= 1)
        m = fmaxf(m, __shfl_xor_sync(0xffffffffu, m, off));
    if (lane == 0) red_s[w] = m;
    __syncthreads();
    if (tid == 0) {
        float mm = red_s[0];
        for (int i = 1; i < 8; i++) mm = fmaxf(mm, red_s[i]);
        red_s[0] = mm;
    }
    __syncthreads();
    float mx = red_s[0];
    float e = (tid < L) ? __expf(x - mx) : 0.f;
    float sv = e;
#pragma unroll
    for (int off = 16; off > 0; off >>= 1)
        sv += __shfl_xor_sync(0xffffffffu, sv, off);
    __syncthreads();
    if (lane == 0) red_s[w] = sv;
    __syncthreads();
    if (tid == 0) {
        float ss = 0.f;
        for (int i = 0; i < 8; i++) ss += red_s[i];
        red_s[0] = ss;
    }
    __syncthreads();
    sc_s[tid] = e * (1.f / red_s[0]);
    __syncthreads();

    float c = 0.f;
    int s = 0;
    for (; s + 4 <= L; s += 4) {
        float v0 = enc[((long)(s + 0) * 32 + b) * 256 + tid];
        float v1 = enc[((long)(s + 1) * 32 + b) * 256 + tid];
        float v2 = enc[((long)(s + 2) * 32 + b) * 256 + tid];
        float v3 = enc[((long)(s + 3) * 32 + b) * 256 + tid];
        c += sc_s[s] * v0 + sc_s[s + 1] * v1 + sc_s[s + 2] * v2 + sc_s[s + 3] * v3;
    }
    for (; s < L; ++s)
        c += sc_s[s] * enc[((long)s * 32 + b) * 256 + tid];

    dctx[(b * 16 + t) * 256 + tid] = c;
    comb[(t * 32 + b) * 512 + tid] = c;
}

// softmax over V=1000 per row (512 rows)
__global__ void softmaxV_kernel(const float* __restrict__ logits,
                                float* __restrict__ prob)
{
    __shared__ float red_s[8];
    int m = blockIdx.x, tid = threadIdx.x, w = tid >> 5, lane = tid & 31;
    const float* row = logits + (long)m * 1000;

    float mx = -1e30f;
    for (int v = tid; v < 1000; v += 256) mx = fmaxf(mx, row[v]);
#pragma unroll
    for (int off = 16; off > 0; off >>= 1)
        mx = fmaxf(mx, __shfl_xor_sync(0xffffffffu, mx, off));
    if (lane == 0) red_s[w] = mx;
    __syncthreads();
    if (tid == 0) {
        float mm = red_s[0];
        for (int i = 1; i < 8; i++) mm = fmaxf(mm, red_s[i]);
        red_s[0] = mm;
    }
    __syncthreads();
    mx = red_s[0];

    float ebuf[4];
    float sum = 0.f;
    int cnt = 0;
    for (int v = tid; v < 1000; v += 256) {
        float e = __expf(row[v] - mx);
        ebuf[cnt++] = e;
        sum += e;
    }
#pragma unroll
    for (int off = 16; off > 0; off >>= 1)
        sum += __shfl_xor_sync(0xffffffffu, sum, off);
    __syncthreads();
    if (lane == 0) red_s[w] = sum;
    __syncthreads();
    if (tid == 0) {
        float ss = 0.f;
        for (int i = 0; i < 8; i++) ss += red_s[i];
        red_s[0] = ss;
    }
    __syncthreads();
    float inv = 1.f / red_s[0];
    cnt = 0;
    for (int v = tid; v < 1000; v += 256)
        prob[(long)m * 1000 + v] = ebuf[cnt++] * inv;
}

extern "C" void kernel_launch(void* const* d_in, const int* in_sizes, int n_in,
                              void* d_out, int out_size)
{
    const int*   target = (const int*)  d_in[0];
    const float* h0     = (const float*)d_in[1];
    const float* c0     = (const float*)d_in[2];
    const float* enc    = (const float*)d_in[3];
    const int*   lens   = (const int*)  d_in[4];
    const float* emb    = (const float*)d_in[5];
    const float* W_ih   = (const float*)d_in[6];
    const float* W_hh   = (const float*)d_in[7];
    const float* b_ih   = (const float*)d_in[8];
    const float* b_hh   = (const float*)d_in[9];
    const float* We     = (const float*)d_in[10];
    const float* be     = (const float*)d_in[11];
    const float* Wd     = (const float*)d_in[12];
    const float* bd     = (const float*)d_in[13];
    const float* wa     = (const float*)d_in[14];
    const float* ba     = (const float*)d_in[15];
    const float* W_out  = (const float*)d_in[16];
    const float* b_out  = (const float*)d_in[17];
    float* out = (float*)d_out;

    float* xproj  = nullptr; cudaGetSymbolAddress((void**)&xproj,  g_xproj);
    float* enct   = nullptr; cudaGetSymbolAddress((void**)&enct,   g_enct);
    float* outh   = nullptr; cudaGetSymbolAddress((void**)&outh,   g_outh);
    float* comb   = nullptr; cudaGetSymbolAddress((void**)&comb,   g_comb);
    float* logits = nullptr; cudaGetSymbolAddress((void**)&logits, g_logits);
    float* WdT    = nullptr; cudaGetSymbolAddress((void**)&WdT,    g_WdT);
    float* scr    = nullptr; cudaGetSymbolAddress((void**)&scr,    g_scores);

    const int LSTM_SMEM = LSTM_SMEM_FLOATS * 4;   // 145728 bytes
    static int smem_set = 0;
    if (!smem_set) {
        cudaFuncSetAttribute(lstm_cluster_kernel,
                             cudaFuncAttributeMaxDynamicSharedMemorySize, LSTM_SMEM);
        smem_set = 1;
    }

    // 0) WdT = Wd^T (tiny; needed by attn_scores)
    transpose256_kernel<<<256, 256>>>(Wd, WdT);
    // 1) x_proj = emb[target] @ W_ih^T + b_ih   [512 x 1024], K=300
    gemm64_kernel<1><<<dim3(16, 8), 128>>>(emb, target, W_ih, b_ih,
                                           xproj, 512, 1024, 300);
    // 2) cluster LSTM (CTAs 0..63) + enc_t workers (CTAs 64..135)
    //    17 clusters total -> single wave under same-die placement
    lstm_cluster_kernel<<<136, 256, LSTM_SMEM>>>(xproj, W_hh, b_hh, h0, c0,
                                                 outh, comb,
                                                 out + HT_OFF, out + CT_OFF,
                                                 enc, lens, We, be, enct);
    // 3a) scores (load-balanced s-quarters)
    attn_scores_kernel<<<dim3(32, 4, 4), 256>>>(enct, outh, WdT, bd, wa, ba,
                                                lens, scr);
    // 3b) softmax + context -> out[CTX], comb(left)
    attn_ctx_kernel<<<dim3(32, 16), 256>>>(scr, enc, lens,
                                           out + CTX_OFF, comb);
    // 4) logits = comb @ W_out^T + b_out   [512 x 1000], K=512
    gemm64_kernel<0><<<dim3(16, 8), 128>>>(comb, nullptr, W_out, b_out,
                                           logits, 512, 1000, 512);
    // 5) softmax over V -> out[PROB]
    softmaxV_kernel<<<512, 256>>>(logits, out + PROB_OFF);
}

// round 16
// speedup vs baseline: 1.1948x; 1.1809x over previous
#include <cuda_runtime.h>
#include <cuda_fp16.h>
#include <math.h>
#include <stdint.h>

// Shapes
#define T_ 16
#define B_ 32
#define S_ 256
#define H_ 256
#define E_ 300
#define V_ 1000

// d_out packing (reference return order, flattened floats)
#define PROB_OFF 0
#define HT_OFF   512000
#define CT_OFF   520192
#define CTX_OFF  528384

// Scratch (device globals; no cudaMalloc allowed)
__device__ float g_xproj[512 * 1024];    // [t*32+b][4H]
__device__ float g_enct[8192 * 256];     // PERMUTED: [b*256+s][H] (masked tiles never read)
__device__ float g_outh[16 * 32 * 256];  // [t][b][h]
__device__ float g_comb[512 * 512];      // [t*32+b][2H]
__device__ float g_logits[512 * 1000];   // [t*32+b][V]
__device__ float g_WdT[256 * 256];       // Wd transposed: [k][h]
__device__ float g_scores[512 * 256];    // raw scores [(t*32+b)][s]

__device__ __forceinline__ float sigmoidf_(float x) {
    return 1.f / (1.f + __expf(-x));
}
__device__ __forceinline__ uint32_t smem_u32(const void* p) {
    uint32_t a;
    asm("{ .reg .u64 t; cvta.to.shared.u64 t, %1; cvt.u32.u64 %0, t; }"
        : "=r"(a) : "l"(p));
    return a;
}
__device__ __forceinline__ void st_cluster_f32(uint32_t addr, uint32_t rank, float v) {
    uint32_t remote;
    asm volatile("mapa.shared::cluster.u32 %0, %1, %2;"
                 : "=r"(remote) : "r"(addr), "r"(rank));
    asm volatile("st.shared::cluster.f32 [%0], %1;"
                 :: "r"(remote), "f"(v) : "memory");
}
__device__ __forceinline__ __half2 tanh_h2(__half2 x) {
    uint32_t xi = *reinterpret_cast<uint32_t*>(&x), yi;
    asm("tanh.approx.f16x2 %0, %1;" : "=r"(yi) : "r"(xi));
    return *reinterpret_cast<__half2*>(&yi);
}

// ---------------------------------------------------------------------------
// GEMM: C[M][N] = Arow(m) . Bw[n] + bias[n]   (B stored [N][K], i.e. C=A@B^T)
// Tile 64(M) x 64(N), TK=8, 128 threads, 8x4 register microtile.
// MODE 0: Arow(m)=A[m]
// MODE 1: Arow(m)=A[Aidx[m]]                  (embedding gather)
// MODE 2: m = b*256+s -> Arow = A[s*32+b]; tile skipped if s0 >= lens[b]
// ---------------------------------------------------------------------------
template <int MODE>
__global__ void __launch_bounds__(128)
gemm64_kernel(const float* __restrict__ A, const int* __restrict__ Aidx,
              const int* __restrict__ lens,
              const float* __restrict__ Bw, const float* __restrict__ bias,
              float* __restrict__ C, int M, int N, int K)
{
    __shared__ __align__(16) float As[8][64];
    __shared__ __align__(16) float Bs[8][64];

    int tid = threadIdx.x;
    int nbase = blockIdx.x * 64, mbase = blockIdx.y * 64;

    if (MODE == 2) {
        int b = mbase >> 8;
        if ((mbase & 255) >= lens[b]) return;   // whole tile masked
    }

    int lr  = tid >> 1;        // 0..63
    int lkq = (tid & 1) * 4;   // 0 or 4

    long arow;
    {
        int m = mbase + lr;
        if (MODE == 1)      arow = Aidx[m];
        else if (MODE == 2) { int b = m >> 8, s = m & 255; arow = (long)s * 32 + b; }
        else                arow = m;
    }
    const float* Ap = A + arow * (long)K;
    int bn = nbase + lr;
    const float* Bp = Bw + (long)bn * K;
    bool bval = (bn < N);

    int tx = tid & 15, ty = tid >> 4;

    float acc[8][4];
#pragma unroll
    for (int i = 0; i < 8; i++)
#pragma unroll
        for (int j = 0; j < 4; j++) acc[i][j] = 0.f;

    int ktiles = (K + 7) >> 3;

    float4 av = make_float4(0.f, 0.f, 0.f, 0.f);
    float4 bv = make_float4(0.f, 0.f, 0.f, 0.f);
    {
        int k = lkq;
        if (k + 3 < K) av = *(const float4*)(Ap + k);
        else { if (k < K) av.x = Ap[k]; if (k+1 < K) av.y = Ap[k+1];
               if (k+2 < K) av.z = Ap[k+2]; if (k+3 < K) av.w = Ap[k+3]; }
        if (bval) {
            if (k + 3 < K) bv = *(const float4*)(Bp + k);
            else { if (k < K) bv.x = Bp[k]; if (k+1 < K) bv.y = Bp[k+1];
                   if (k+2 < K) bv.z = Bp[k+2]; if (k+3 < K) bv.w = Bp[k+3]; }
        }
    }

    for (int kt = 0; kt < ktiles; ++kt) {
        __syncthreads();
        As[lkq + 0][lr] = av.x; As[lkq + 1][lr] = av.y;
        As[lkq + 2][lr] = av.z; As[lkq + 3][lr] = av.w;
        Bs[lkq + 0][lr] = bv.x; Bs[lkq + 1][lr] = bv.y;
        Bs[lkq + 2][lr] = bv.z; Bs[lkq + 3][lr] = bv.w;
        __syncthreads();

        av = make_float4(0.f, 0.f, 0.f, 0.f);
        bv = make_float4(0.f, 0.f, 0.f, 0.f);
        if (kt + 1 < ktiles) {
            int k = ((kt + 1) << 3) + lkq;
            if (k + 3 < K) av = *(const float4*)(Ap + k);
            else { if (k < K) av.x = Ap[k]; if (k+1 < K) av.y = Ap[k+1];
                   if (k+2 < K) av.z = Ap[k+2]; if (k+3 < K) av.w = Ap[k+3]; }
            if (bval) {
                if (k + 3 < K) bv = *(const float4*)(Bp + k);
                else { if (k < K) bv.x = Bp[k]; if (k+1 < K) bv.y = Bp[k+1];
                       if (k+2 < K) bv.z = Bp[k+2]; if (k+3 < K) bv.w = Bp[k+3]; }
            }
        }

#pragma unroll
        for (int k = 0; k < 8; ++k) {
            float4 a0 = *(const float4*)&As[k][ty * 4];
            float4 a1 = *(const float4*)&As[k][32 + ty * 4];
            float4 b  = *(const float4*)&Bs[k][tx * 4];
            acc[0][0] += a0.x * b.x; acc[0][1] += a0.x * b.y; acc[0][2] += a0.x * b.z; acc[0][3] += a0.x * b.w;
            acc[1][0] += a0.y * b.x; acc[1][1] += a0.y * b.y; acc[1][2] += a0.y * b.z; acc[1][3] += a0.y * b.w;
            acc[2][0] += a0.z * b.x; acc[2][1] += a0.z * b.y; acc[2][2] += a0.z * b.z; acc[2][3] += a0.z * b.w;
            acc[3][0] += a0.w * b.x; acc[3][1] += a0.w * b.y; acc[3][2] += a0.w * b.z; acc[3][3] += a0.w * b.w;
            acc[4][0] += a1.x * b.x; acc[4][1] += a1.x * b.y; acc[4][2] += a1.x * b.z; acc[4][3] += a1.x * b.w;
            acc[5][0] += a1.y * b.x; acc[5][1] += a1.y * b.y; acc[5][2] += a1.y * b.z; acc[5][3] += a1.y * b.w;
            acc[6][0] += a1.z * b.x; acc[6][1] += a1.z * b.y; acc[6][2] += a1.z * b.z; acc[6][3] += a1.z * b.w;
            acc[7][0] += a1.w * b.x; acc[7][1] += a1.w * b.y; acc[7][2] += a1.w * b.z; acc[7][3] += a1.w * b.w;
        }
    }

#pragma unroll
    for (int i = 0; i < 8; i++) {
        int mm = mbase + ((i < 4) ? (ty * 4 + i) : (32 + ty * 4 + (i - 4)));
#pragma unroll
        for (int j = 0; j < 4; j++) {
            int n = nbase + tx * 4 + j;
            if (n < N) C[(long)mm * N + n] = acc[i][j] + bias[n];
        }
    }
}

// Naive transpose: WdT[k][h] = Wd[h][k]  (256x256, tiny)
__global__ void transpose256_kernel(const float* __restrict__ in,
                                    float* __restrict__ out)
{
    int idx = blockIdx.x * 256 + threadIdx.x;  // idx = k*256 + h
    int k = idx >> 8, h = idx & 255;
    out[idx] = in[h * 256 + k];
}

// ---------------------------------------------------------------------------
// Cluster LSTM: 64 CTAs = 8 clusters x 8 CTAs, 256 threads each. (pure R10
// kernel — measured 69.5 us standalone.)
// ---------------------------------------------------------------------------
#define LSTM_HS 33792
#define LSTM_GS 35904
#define LSTM_SMEM_FLOATS 36432

__global__ void __launch_bounds__(256, 1) __cluster_dims__(8, 1, 1)
lstm_cluster_kernel(const float* __restrict__ xproj, const float* __restrict__ W_hh,
                    const float* __restrict__ b_hh, const float* __restrict__ h0,
                    const float* __restrict__ c0, float* __restrict__ outh,
                    float* __restrict__ comb,
                    float* __restrict__ dhT, float* __restrict__ dcT)
{
    extern __shared__ __align__(16) float sm[];
    float* W_sm = sm;

    int tid = threadIdx.x;
    uint32_t rank;
    asm("mov.u32 %0, %%cluster_ctarank;" : "=r"(rank));
    int B0 = (blockIdx.x >> 3) * 4;
    int u_base = 32 * (int)rank;

    for (int i = tid; i < 32768; i += 256) {
        int row = i >> 8, k = i & 255;
        int g = row >> 5, ul = row & 31;
        W_sm[k * 132 + row] = W_hh[(g * 256 + u_base + ul) * 256 + k];
    }
    for (int i = tid; i < 1024; i += 256) {
        int b = i >> 8, k = i & 255;
        sm[LSTM_HS + b * 264 + k] = h0[(B0 + b) * 256 + k];
    }

    float bh[4], cprev = 0.f;
    int ful = tid >> 2, fb = tid & 3;
    if (tid < 128) {
#pragma unroll
        for (int g = 0; g < 4; g++) bh[g] = b_hh[g * 256 + u_base + ful];
        cprev = c0[(B0 + fb) * 256 + u_base + ful];
    }
    __syncthreads();
    asm volatile("barrier.cluster.arrive.aligned;" ::: "memory");
    asm volatile("barrier.cluster.wait.aligned;"   ::: "memory");

    uint32_t smb_hs = smem_u32(sm + LSTM_HS);

    int row = tid & 127;
    int bh2 = tid >> 7;

    for (int t = 0; t < 16; ++t) {
        int buf = t & 1;

        float xp[4];
        if (tid < 128) {
#pragma unroll
            for (int g = 0; g < 4; g++)
                xp[g] = __ldg(xproj + (long)(t * 32 + B0 + fb) * 1024
                                    + g * 256 + u_base + ful);
        }

        const float* hA = sm + LSTM_HS + buf * 1056 + (bh2 * 2) * 264;
        const float* hB = hA + 264;
        float a0 = 0.f, a1 = 0.f;
#pragma unroll 8
        for (int k = 0; k < 256; k += 4) {
            float w0 = W_sm[(k + 0) * 132 + row];
            float w1 = W_sm[(k + 1) * 132 + row];
            float w2 = W_sm[(k + 2) * 132 + row];
            float w3 = W_sm[(k + 3) * 132 + row];
            float4 ha = *(const float4*)(hA + k);
            float4 hb = *(const float4*)(hB + k);
            a0 += w0 * ha.x + w1 * ha.y + w2 * ha.z + w3 * ha.w;
            a1 += w0 * hb.x + w1 * hb.y + w2 * hb.z + w3 * hb.w;
        }
        sm[LSTM_GS + (bh2 * 2 + 0) * 132 + row] = a0;
        sm[LSTM_GS + (bh2 * 2 + 1) * 132 + row] = a1;
        __syncthreads();

        if (tid < 128) {
            float gi = sm[LSTM_GS + fb * 132 +  0 + ful] + xp[0] + bh[0];
            float gf = sm[LSTM_GS + fb * 132 + 32 + ful] + xp[1] + bh[1];
            float gg = sm[LSTM_GS + fb * 132 + 64 + ful] + xp[2] + bh[2];
            float go = sm[LSTM_GS + fb * 132 + 96 + ful] + xp[3] + bh[3];
            float c = sigmoidf_(gf) * cprev + sigmoidf_(gi) * tanhf(gg);
            float h = sigmoidf_(go) * tanhf(c);
            cprev = c;
            int hu = u_base + ful;
            int gb = B0 + fb;
            outh[t * 8192 + gb * 256 + hu] = h;
            comb[(t * 32 + gb) * 512 + 256 + hu] = h;
            if (t == 15) {
                dhT[gb * 256 + hu] = h;
                dcT[gb * 256 + hu] = c;
            } else {
                uint32_t off = smb_hs
                             + ((uint32_t)(((buf ^ 1) * 1056) + fb * 264 + hu) << 2);
#pragma unroll
                for (uint32_t r = 0; r < 8; r++) st_cluster_f32(off, r, h);
            }
        }

        if (t < 15) {
            asm volatile("barrier.cluster.arrive.aligned;" ::: "memory");
            asm volatile("barrier.cluster.wait.aligned;"   ::: "memory");
        }
    }
}

// ---------------------------------------------------------------------------
// Attention scores (load-balanced): grid (b=32, tg=4, sq=4), 256 threads.
// ---------------------------------------------------------------------------
__global__ void __launch_bounds__(256)
attn_scores_kernel(const float* __restrict__ enct,   // [b*256+s][H]
                   const float* __restrict__ outh,   // [t][b][h]
                   const float* __restrict__ WdT,    // [k][h]
                   const float* __restrict__ bd,
                   const float* __restrict__ wa,
                   const float* __restrict__ ba,
                   const int* __restrict__ lens,
                   float* __restrict__ scores)       // [(t*32+b)][s]
{
    __shared__ __align__(16) float outh_s[4][256];
    __shared__ __align__(16) float dec_s[4][256];
    __shared__ __align__(4) __half2 wa_h2[128];

    int b = blockIdx.x, t0 = blockIdx.y * 4, s0 = blockIdx.z * 64;
    int tid = threadIdx.x;
    int L = lens[b];
    if (s0 >= L) return;
    int send = min(s0 + 64, L);
    int w = tid >> 5, lane = tid & 31;

    {
        int j = tid >> 6, q = (tid & 63) * 4;
        float4 v = *(const float4*)(outh + (t0 + j) * 8192 + b * 256 + q);
        *(float4*)&outh_s[j][q] = v;
    }
    if (tid < 128)
        wa_h2[tid] = __floats2half2_rn(wa[2 * tid], wa[2 * tid + 1]);
    float bav = ba[0];
    __syncthreads();

    // dec_t: thread h = tid (fma pipe; overlaps other warps' MUFU)
    {
        float a0 = 0.f, a1 = 0.f, a2 = 0.f, a3 = 0.f;
#pragma unroll 4
        for (int k = 0; k < 256; k += 4) {
            float w0 = WdT[(k + 0) * 256 + tid];
            float w1 = WdT[(k + 1) * 256 + tid];
            float w2 = WdT[(k + 2) * 256 + tid];
            float w3 = WdT[(k + 3) * 256 + tid];
            float4 o0 = *(const float4*)&outh_s[0][k];
            float4 o1 = *(const float4*)&outh_s[1][k];
            float4 o2 = *(const float4*)&outh_s[2][k];
            float4 o3 = *(const float4*)&outh_s[3][k];
            a0 += w0 * o0.x + w1 * o0.y + w2 * o0.z + w3 * o0.w;
            a1 += w0 * o1.x + w1 * o1.y + w2 * o1.z + w3 * o1.w;
            a2 += w0 * o2.x + w1 * o2.y + w2 * o2.z + w3 * o2.w;
            a3 += w0 * o3.x + w1 * o3.y + w2 * o3.z + w3 * o3.w;
        }
        float bdv = bd[tid];
        dec_s[0][tid] = a0 + bdv;
        dec_s[1][tid] = a1 + bdv;
        dec_s[2][tid] = a2 + bdv;
        dec_s[3][tid] = a3 + bdv;
    }
    __syncthreads();

    float2 dpr[4][4];   // [j][t]
    __half2 wa2r[4];
#pragma unroll
    for (int j = 0; j < 4; j++) {
        int p = lane + 32 * j;
        wa2r[j] = wa_h2[p];
#pragma unroll
        for (int tt = 0; tt < 4; tt++)
            dpr[j][tt] = *(const float2*)&dec_s[tt][2 * p];
    }
    __half2 zero2 = __floats2half2_rn(0.f, 0.f);

    for (int s = s0 + w; s < send; s += 8) {
        const float2* eb2 = (const float2*)(enct + ((long)b * 256 + s) * 256);
        __half2 a0 = zero2, a1 = zero2, a2 = zero2, a3 = zero2;
#pragma unroll
        for (int j = 0; j < 4; j++) {
            float2 e = eb2[lane + 32 * j];
            __half2 w2 = wa2r[j];
            a0 = __hfma2(tanh_h2(__floats2half2_rn(e.x + dpr[j][0].x, e.y + dpr[j][0].y)), w2, a0);
            a1 = __hfma2(tanh_h2(__floats2half2_rn(e.x + dpr[j][1].x, e.y + dpr[j][1].y)), w2, a1);
            a2 = __hfma2(tanh_h2(__floats2half2_rn(e.x + dpr[j][2].x, e.y + dpr[j][2].y)), w2, a2);
            a3 = __hfma2(tanh_h2(__floats2half2_rn(e.x + dpr[j][3].x, e.y + dpr[j][3].y)), w2, a3);
        }
        float2 f0 = __half22float2(a0), f1 = __half22float2(a1);
        float2 f2 = __half22float2(a2), f3 = __half22float2(a3);
        float p0 = f0.x + f0.y, p1 = f1.x + f1.y;
        float p2 = f2.x + f2.y, p3 = f3.x + f3.y;
#pragma unroll
        for (int off = 16; off > 0; off >>= 1) {
            p0 += __shfl_xor_sync(0xffffffffu, p0, off);
            p1 += __shfl_xor_sync(0xffffffffu, p1, off);
            p2 += __shfl_xor_sync(0xffffffffu, p2, off);
            p3 += __shfl_xor_sync(0xffffffffu, p3, off);
        }
        if (lane == 0) {
            scores[((t0 + 0) * 32 + b) * 256 + s] = p0 + bav;
            scores[((t0 + 1) * 32 + b) * 256 + s] = p1 + bav;
            scores[((t0 + 2) * 32 + b) * 256 + s] = p2 + bav;
            scores[((t0 + 3) * 32 + b) * 256 + s] = p3 + bav;
        }
    }
}

// ---------------------------------------------------------------------------
// Attention softmax + context: grid (b=32, t=16) = 512 CTAs, 256 threads.
// ---------------------------------------------------------------------------
__global__ void __launch_bounds__(256)
attn_ctx_kernel(const float* __restrict__ scores,  // [(t*32+b)][s]
                const float* __restrict__ enc,     // [s*32+b][H]
                const int* __restrict__ lens,
                float* __restrict__ dctx,          // out + CTX_OFF, [b][t][h]
                float* __restrict__ comb)          // [t*32+b][2H]
{
    __shared__ float sc_s[256];
    __shared__ float red_s[8];

    int b = blockIdx.x, t = blockIdx.y, tid = threadIdx.x;
    int w = tid >> 5, lane = tid & 31;
    int L = lens[b];

    float x = (tid < L) ? scores[(t * 32 + b) * 256 + tid] : -1e30f;
    float m = x;
#pragma unroll
    for (int off = 16; off > 0; off >>= 1)
        m = fmaxf(m, __shfl_xor_sync(0xffffffffu, m, off));
    if (lane == 0) red_s[w] = m;
    __syncthreads();
    if (tid == 0) {
        float mm = red_s[0];
        for (int i = 1; i < 8; i++) mm = fmaxf(mm, red_s[i]);
        red_s[0] = mm;
    }
    __syncthreads();
    float mx = red_s[0];
    float e = (tid < L) ? __expf(x - mx) : 0.f;
    float sv = e;
#pragma unroll
    for (int off = 16; off > 0; off >>= 1)
        sv += __shfl_xor_sync(0xffffffffu, sv, off);
    __syncthreads();
    if (lane == 0) red_s[w] = sv;
    __syncthreads();
    if (tid == 0) {
        float ss = 0.f;
        for (int i = 0; i < 8; i++) ss += red_s[i];
        red_s[0] = ss;
    }
    __syncthreads();
    sc_s[tid] = e * (1.f / red_s[0]);
    __syncthreads();

    float c = 0.f;
    int s = 0;
    for (; s + 4 <= L; s += 4) {
        float v0 = enc[((long)(s + 0) * 32 + b) * 256 + tid];
        float v1 = enc[((long)(s + 1) * 32 + b) * 256 + tid];
        float v2 = enc[((long)(s + 2) * 32 + b) * 256 + tid];
        float v3 = enc[((long)(s + 3) * 32 + b) * 256 + tid];
        c += sc_s[s] * v0 + sc_s[s + 1] * v1 + sc_s[s + 2] * v2 + sc_s[s + 3] * v3;
    }
    for (; s < L; ++s)
        c += sc_s[s] * enc[((long)s * 32 + b) * 256 + tid];

    dctx[(b * 16 + t) * 256 + tid] = c;
    comb[(t * 32 + b) * 512 + tid] = c;
}

// softmax over V=1000 per row (512 rows)
__global__ void softmaxV_kernel(const float* __restrict__ logits,
                                float* __restrict__ prob)
{
    __shared__ float red_s[8];
    int m = blockIdx.x, tid = threadIdx.x, w = tid >> 5, lane = tid & 31;
    const float* row = logits + (long)m * 1000;

    float mx = -1e30f;
    for (int v = tid; v < 1000; v += 256) mx = fmaxf(mx, row[v]);
#pragma unroll
    for (int off = 16; off > 0; off >>= 1)
        mx = fmaxf(mx, __shfl_xor_sync(0xffffffffu, mx, off));
    if (lane == 0) red_s[w] = mx;
    __syncthreads();
    if (tid == 0) {
        float mm = red_s[0];
        for (int i = 1; i < 8; i++) mm = fmaxf(mm, red_s[i]);
        red_s[0] = mm;
    }
    __syncthreads();
    mx = red_s[0];

    float ebuf[4];
    float sum = 0.f;
    int cnt = 0;
    for (int v = tid; v < 1000; v += 256) {
        float e = __expf(row[v] - mx);
        ebuf[cnt++] = e;
        sum += e;
    }
#pragma unroll
    for (int off = 16; off > 0; off >>= 1)
        sum += __shfl_xor_sync(0xffffffffu, sum, off);
    __syncthreads();
    if (lane == 0) red_s[w] = sum;
    __syncthreads();
    if (tid == 0) {
        float ss = 0.f;
        for (int i = 0; i < 8; i++) ss += red_s[i];
        red_s[0] = ss;
    }
    __syncthreads();
    float inv = 1.f / red_s[0];
    cnt = 0;
    for (int v = tid; v < 1000; v += 256)
        prob[(long)m * 1000 + v] = ebuf[cnt++] * inv;
}

extern "C" void kernel_launch(void* const* d_in, const int* in_sizes, int n_in,
                              void* d_out, int out_size)
{
    const int*   target = (const int*)  d_in[0];
    const float* h0     = (const float*)d_in[1];
    const float* c0     = (const float*)d_in[2];
    const float* enc    = (const float*)d_in[3];
    const int*   lens   = (const int*)  d_in[4];
    const float* emb    = (const float*)d_in[5];
    const float* W_ih   = (const float*)d_in[6];
    const float* W_hh   = (const float*)d_in[7];
    const float* b_ih   = (const float*)d_in[8];
    const float* b_hh   = (const float*)d_in[9];
    const float* We     = (const float*)d_in[10];
    const float* be     = (const float*)d_in[11];
    const float* Wd     = (const float*)d_in[12];
    const float* bd     = (const float*)d_in[13];
    const float* wa     = (const float*)d_in[14];
    const float* ba     = (const float*)d_in[15];
    const float* W_out  = (const float*)d_in[16];
    const float* b_out  = (const float*)d_in[17];
    float* out = (float*)d_out;

    float* xproj  = nullptr; cudaGetSymbolAddress((void**)&xproj,  g_xproj);
    float* enct   = nullptr; cudaGetSymbolAddress((void**)&enct,   g_enct);
    float* outh   = nullptr; cudaGetSymbolAddress((void**)&outh,   g_outh);
    float* comb   = nullptr; cudaGetSymbolAddress((void**)&comb,   g_comb);
    float* logits = nullptr; cudaGetSymbolAddress((void**)&logits, g_logits);
    float* WdT    = nullptr; cudaGetSymbolAddress((void**)&WdT,    g_WdT);
    float* scr    = nullptr; cudaGetSymbolAddress((void**)&scr,    g_scores);

    const int LSTM_SMEM = LSTM_SMEM_FLOATS * 4;   // 145728 bytes
    static int smem_set = 0;
    if (!smem_set) {
        cudaFuncSetAttribute(lstm_cluster_kernel,
                             cudaFuncAttributeMaxDynamicSharedMemorySize, LSTM_SMEM);
        smem_set = 1;
    }

    // 0) WdT = Wd^T (tiny; needed by attn_scores)
    transpose256_kernel<<<256, 256>>>(Wd, WdT);
    // 1) x_proj = emb[target] @ W_ih^T + b_ih   [512 x 1024], K=300
    gemm64_kernel<1><<<dim3(16, 8), 128>>>(emb, target, nullptr, W_ih, b_ih,
                                           xproj, 512, 1024, 300);
    // 2) enc_t (permuted [b][s][h]) = enc @ We^T + be, masked tiles skipped
    //    512 light CTAs -> 3.5 CTAs/SM, latency-hidden
    gemm64_kernel<2><<<dim3(4, 128), 128>>>(enc, nullptr, lens, We, be,
                                            enct, 8192, 256, 256);
    // 3) cluster LSTM (pure, 64 CTAs = 8 clusters) -> outh, comb(right), hT, cT
    lstm_cluster_kernel<<<64, 256, LSTM_SMEM>>>(xproj, W_hh, b_hh, h0, c0,
                                                outh, comb,
                                                out + HT_OFF, out + CT_OFF);
    // 4a) scores (load-balanced s-quarters)
    attn_scores_kernel<<<dim3(32, 4, 4), 256>>>(enct, outh, WdT, bd, wa, ba,
                                                lens, scr);
    // 4b) softmax + context -> out[CTX], comb(left)
    attn_ctx_kernel<<<dim3(32, 16), 256>>>(scr, enc, lens,
                                           out + CTX_OFF, comb);
    // 5) logits = comb @ W_out^T + b_out   [512 x 1000], K=512
    gemm64_kernel<0><<<dim3(16, 8), 128>>>(comb, nullptr, nullptr, W_out, b_out,
                                           logits, 512, 1000, 512);
    // 6) softmax over V -> out[PROB]
    softmaxV_kernel<<<512, 256>>>(logits, out + PROB_OFF);
}